// round 1
// baseline (speedup 1.0000x reference)
#include <cuda_runtime.h>
#include <cuda_bf16.h>
#include <math.h>

// Problem constants (fixed-shape problem)
#define DHID    64
#define HEADS   4
#define C1      256      // HEADS*DHID
#define DIM     128      // emb dim
#define SLOPE   0.2f

#define MAXN    20480
#define MAXET   345088   // E + N with margin (320000+20000)

// ---------------- scratch (static device globals; no allocation) ------------
__device__ float g_h1[MAXN * C1];      // layer1 pre-activation features
__device__ float g_x2[MAXN * C1];      // layer1 output (elu)
__device__ float g_h2[MAXN * DHID];    // layer2 pre-agg features
__device__ float g_x3[MAXN * DHID];    // layer2 output (elu)
__device__ float g_asrc1[MAXN * HEADS];
__device__ float g_adst1[MAXN * HEADS];
__device__ float g_asrc2[MAXN];
__device__ float g_adst2[MAXN];
__device__ int   g_deg[MAXN];
__device__ int   g_cursor[MAXN];
__device__ int   g_rowstart[MAXN + 1];
__device__ int   g_srcs[MAXET];
__device__ float g_gate[MAXN];
__device__ float g_w[MAXN];
__device__ float g_gmax;
__device__ float g_S;

// ---------------- init ----------------
__global__ void k_init(int n) {
    int i = blockIdx.x * blockDim.x + threadIdx.x;
    if (i < n) { g_deg[i] = 0; g_cursor[i] = 0; }
    if (i == 0) { g_S = 0.f; }
}

// ---------------- CSR build ----------------
__global__ void k_count(const int* __restrict__ ei, int E, int n) {
    int i = blockIdx.x * blockDim.x + threadIdx.x;
    int ET = E + n;
    if (i >= ET) return;
    int dst = (i < E) ? ei[E + i] : (i - E);
    atomicAdd(&g_deg[dst], 1);
}

__global__ void k_scan(int n) {
    __shared__ int ps[1024];
    int tid = threadIdx.x;
    int chunk = (n + 1023) / 1024;
    int s0 = tid * chunk, s1 = min(s0 + chunk, n);
    int sum = 0;
    for (int i = s0; i < s1; i++) sum += g_deg[i];
    ps[tid] = sum;
    __syncthreads();
    if (tid == 0) {
        int run = 0;
        for (int i = 0; i < 1024; i++) { int t = ps[i]; ps[i] = run; run += t; }
        g_rowstart[n] = run;
    }
    __syncthreads();
    int run = ps[tid];
    for (int i = s0; i < s1; i++) { g_rowstart[i] = run; run += g_deg[i]; }
}

__global__ void k_fill(const int* __restrict__ ei, int E, int n) {
    int i = blockIdx.x * blockDim.x + threadIdx.x;
    int ET = E + n;
    if (i >= ET) return;
    int src, dst;
    if (i < E) { src = ei[i]; dst = ei[E + i]; } else { src = dst = i - E; }
    int p = atomicAdd(&g_cursor[dst], 1);
    g_srcs[g_rowstart[dst] + p] = src;
}

// ---------------- tiled SGEMM (optionally row-gathered A) ----------------
// C[M,Ncols] = A[M,K] @ B[K,Ncols];  if ridx != nullptr, A row m is emb[ridx[m]*K .. ]
#define BM 64
#define BN 64
#define BK 16
__global__ __launch_bounds__(256) void k_gemm(
    const float* __restrict__ A, const float* __restrict__ B, float* __restrict__ C,
    int M, int K, int Ncols, const int* __restrict__ ridx, const float* __restrict__ emb)
{
    __shared__ float As[BK][BM];
    __shared__ float Bs[BK][BN];
    __shared__ int   rs[BM];
    int row0 = blockIdx.x * BM;
    int col0 = blockIdx.y * BN;
    int tid = threadIdx.x;
    if (ridx && tid < BM) {
        int r = row0 + tid;
        rs[tid] = (r < M) ? ridx[r] * K : 0;
    }
    float acc[4][4] = {};
    int tx = tid & 15, ty = tid >> 4;
    for (int k0 = 0; k0 < K; k0 += BK) {
        __syncthreads();
        #pragma unroll
        for (int t = 0; t < (BM * BK) / 256; t++) {
            int e = tid + 256 * t;
            int m = e / BK, k = e % BK;
            int gr = row0 + m;
            float v = 0.f;
            if (gr < M) {
                const float* Arow = ridx ? (emb + rs[m]) : (A + (size_t)gr * K);
                v = Arow[k0 + k];
            }
            As[k][m] = v;
        }
        #pragma unroll
        for (int t = 0; t < (BK * BN) / 256; t++) {
            int e = tid + 256 * t;
            int k = e / BN, c = e % BN;
            int gc = col0 + c;
            Bs[k][c] = (gc < Ncols) ? B[(size_t)(k0 + k) * Ncols + gc] : 0.f;
        }
        __syncthreads();
        #pragma unroll
        for (int k = 0; k < BK; k++) {
            float a[4], b[4];
            #pragma unroll
            for (int i = 0; i < 4; i++) a[i] = As[k][ty * 4 + i];
            #pragma unroll
            for (int j = 0; j < 4; j++) b[j] = Bs[k][tx * 4 + j];
            #pragma unroll
            for (int i = 0; i < 4; i++)
                #pragma unroll
                for (int j = 0; j < 4; j++) acc[i][j] += a[i] * b[j];
        }
    }
    #pragma unroll
    for (int i = 0; i < 4; i++) {
        int r = row0 + ty * 4 + i;
        if (r >= M) continue;
        #pragma unroll
        for (int j = 0; j < 4; j++) {
            int c = col0 + tx * 4 + j;
            if (c < Ncols) C[(size_t)r * Ncols + c] = acc[i][j];
        }
    }
}

// ---------------- alpha for layer 1 (4 heads, 64 ch each) ----------------
__global__ __launch_bounds__(256) void k_alpha1(
    const float* __restrict__ h1, const float* __restrict__ att_src,
    const float* __restrict__ att_dst, int n)
{
    int gw = (blockIdx.x * blockDim.x + threadIdx.x) >> 5;
    int lane = threadIdx.x & 31;
    if (gw >= n) return;
    int head = lane >> 3;
    const float4* hp = (const float4*)(h1 + (size_t)gw * C1 + lane * 8);
    const float4* sp = (const float4*)(att_src + lane * 8);
    const float4* dp = (const float4*)(att_dst + lane * 8);
    float4 v0 = hp[0], v1 = hp[1];
    float4 s0 = sp[0], s1 = sp[1];
    float4 d0 = dp[0], d1 = dp[1];
    float s = v0.x * s0.x + v0.y * s0.y + v0.z * s0.z + v0.w * s0.w
            + v1.x * s1.x + v1.y * s1.y + v1.z * s1.z + v1.w * s1.w;
    float d = v0.x * d0.x + v0.y * d0.y + v0.z * d0.z + v0.w * d0.w
            + v1.x * d1.x + v1.y * d1.y + v1.z * d1.z + v1.w * d1.w;
    #pragma unroll
    for (int o = 4; o; o >>= 1) {
        s += __shfl_xor_sync(0xFFFFFFFFu, s, o);
        d += __shfl_xor_sync(0xFFFFFFFFu, d, o);
    }
    if ((lane & 7) == 0) {
        g_asrc1[gw * HEADS + head] = s;
        g_adst1[gw * HEADS + head] = d;
    }
}

// ---------------- layer1 aggregation: warp per dst node ----------------
__global__ __launch_bounds__(256) void k_agg1(
    const float* __restrict__ h1, const float* __restrict__ b1, int n)
{
    int gw = (blockIdx.x * blockDim.x + threadIdx.x) >> 5;
    int lane = threadIdx.x & 31;
    if (gw >= n) return;
    int head = lane >> 3;
    int s0 = g_rowstart[gw], s1 = g_rowstart[gw + 1];
    float adst_n = g_adst1[gw * HEADS + head];
    float m = -1e30f;
    for (int e = s0; e < s1; e++) {
        int src = g_srcs[e];
        float l = g_asrc1[src * HEADS + head] + adst_n;
        l = l > 0.f ? l : SLOPE * l;
        m = fmaxf(m, l);
    }
    float acc[8] = {0, 0, 0, 0, 0, 0, 0, 0};
    float se = 0.f;
    for (int e = s0; e < s1; e++) {
        int src = g_srcs[e];
        float l = g_asrc1[src * HEADS + head] + adst_n;
        l = l > 0.f ? l : SLOPE * l;
        float p = __expf(l - m);
        se += p;
        const float4* hp = (const float4*)(h1 + (size_t)src * C1 + lane * 8);
        float4 v0 = hp[0], v1 = hp[1];
        acc[0] += p * v0.x; acc[1] += p * v0.y; acc[2] += p * v0.z; acc[3] += p * v0.w;
        acc[4] += p * v1.x; acc[5] += p * v1.y; acc[6] += p * v1.z; acc[7] += p * v1.w;
    }
    float inv = 1.f / se;
    #pragma unroll
    for (int j = 0; j < 8; j++) {
        int c = lane * 8 + j;
        float v = acc[j] * inv + b1[c];
        g_x2[(size_t)gw * C1 + c] = v > 0.f ? v : expm1f(v);
    }
}

// ---------------- alpha for layer 2 (1 head, 64 ch) ----------------
__global__ __launch_bounds__(256) void k_alpha2(
    const float* __restrict__ h2, const float* __restrict__ att_src,
    const float* __restrict__ att_dst, int n)
{
    int gw = (blockIdx.x * blockDim.x + threadIdx.x) >> 5;
    int lane = threadIdx.x & 31;
    if (gw >= n) return;
    float va = h2[(size_t)gw * DHID + lane];
    float vb = h2[(size_t)gw * DHID + lane + 32];
    float s = va * att_src[lane] + vb * att_src[lane + 32];
    float d = va * att_dst[lane] + vb * att_dst[lane + 32];
    #pragma unroll
    for (int o = 16; o; o >>= 1) {
        s += __shfl_xor_sync(0xFFFFFFFFu, s, o);
        d += __shfl_xor_sync(0xFFFFFFFFu, d, o);
    }
    if (lane == 0) { g_asrc2[gw] = s; g_adst2[gw] = d; }
}

// ---------------- layer2 aggregation ----------------
__global__ __launch_bounds__(256) void k_agg2(
    const float* __restrict__ h2, const float* __restrict__ b2, int n)
{
    int gw = (blockIdx.x * blockDim.x + threadIdx.x) >> 5;
    int lane = threadIdx.x & 31;
    if (gw >= n) return;
    int s0 = g_rowstart[gw], s1 = g_rowstart[gw + 1];
    float adst_n = g_adst2[gw];
    float m = -1e30f;
    for (int e = s0; e < s1; e++) {
        int src = g_srcs[e];
        float l = g_asrc2[src] + adst_n;
        l = l > 0.f ? l : SLOPE * l;
        m = fmaxf(m, l);
    }
    float a0 = 0.f, a1 = 0.f, se = 0.f;
    for (int e = s0; e < s1; e++) {
        int src = g_srcs[e];
        float l = g_asrc2[src] + adst_n;
        l = l > 0.f ? l : SLOPE * l;
        float p = __expf(l - m);
        se += p;
        const float2* hp = (const float2*)(h2 + (size_t)src * DHID + lane * 2);
        float2 v = hp[0];
        a0 += p * v.x; a1 += p * v.y;
    }
    float inv = 1.f / se;
    float o0 = a0 * inv + b2[lane * 2];
    float o1 = a1 * inv + b2[lane * 2 + 1];
    g_x3[(size_t)gw * DHID + lane * 2]     = o0 > 0.f ? o0 : expm1f(o0);
    g_x3[(size_t)gw * DHID + lane * 2 + 1] = o1 > 0.f ? o1 : expm1f(o1);
}

// ---------------- gate MLP: warp per node ----------------
__global__ __launch_bounds__(256) void k_gate(
    const float* __restrict__ gW1, const float* __restrict__ gb1,
    const float* __restrict__ gW2, const float* __restrict__ gb2, int n)
{
    __shared__ float Ws[DHID * DHID];
    __shared__ float xr[8][DHID];
    int tid = threadIdx.x;
    for (int i = tid; i < DHID * DHID; i += 256) Ws[i] = gW1[i];
    int w = tid >> 5, lane = tid & 31;
    int node = blockIdx.x * 8 + w;
    __syncthreads();
    if (node >= n) return;
    xr[w][lane]      = g_x3[(size_t)node * DHID + lane];
    xr[w][lane + 32] = g_x3[(size_t)node * DHID + lane + 32];
    __syncwarp();
    float a0 = gb1[lane], a1 = gb1[lane + 32];
    #pragma unroll 8
    for (int k = 0; k < DHID; k++) {
        float xv = xr[w][k];
        a0 += xv * Ws[k * DHID + lane];
        a1 += xv * Ws[k * DHID + lane + 32];
    }
    a0 = fmaxf(a0, 0.f); a1 = fmaxf(a1, 0.f);
    float g = a0 * gW2[lane] + a1 * gW2[lane + 32];
    #pragma unroll
    for (int o = 16; o; o >>= 1) g += __shfl_xor_sync(0xFFFFFFFFu, g, o);
    if (lane == 0) g_gate[node] = g + gb2[0];
}

// ---------------- global max of gate (single block) ----------------
__global__ void k_gmax(int n) {
    __shared__ float red[1024];
    int tid = threadIdx.x;
    float m = -1e30f;
    for (int i = tid; i < n; i += 1024) m = fmaxf(m, g_gate[i]);
    red[tid] = m;
    __syncthreads();
    for (int o = 512; o; o >>= 1) {
        if (tid < o) red[tid] = fmaxf(red[tid], red[tid + o]);
        __syncthreads();
    }
    if (tid == 0) g_gmax = red[0];
}

// ---------------- softmax weights + sum ----------------
__global__ void k_weights(int n) {
    __shared__ float red[256];
    int tid = threadIdx.x;
    int i = blockIdx.x * 256 + tid;
    float v = 0.f;
    if (i < n) { v = __expf(g_gate[i] - g_gmax); g_w[i] = v; }
    red[tid] = v;
    __syncthreads();
    for (int o = 128; o; o >>= 1) {
        if (tid < o) red[tid] += red[tid + o];
        __syncthreads();
    }
    if (tid == 0) atomicAdd(&g_S, red[0]);
}

// ---------------- final weighted pool: one block per channel ----------------
__global__ void k_pool(float* __restrict__ out, int n) {
    __shared__ float red[256];
    int c = blockIdx.x;
    int tid = threadIdx.x;
    float s = 0.f;
    for (int i = tid; i < n; i += 256) s += g_w[i] * g_x3[(size_t)i * DHID + c];
    red[tid] = s;
    __syncthreads();
    for (int o = 128; o; o >>= 1) {
        if (tid < o) red[tid] += red[tid + o];
        __syncthreads();
    }
    if (tid == 0) out[c] = red[0] / g_S;
}

// ---------------- launch ----------------
extern "C" void kernel_launch(void* const* d_in, const int* in_sizes, int n_in,
                              void* d_out, int out_size) {
    const int*   node_idxs = (const int*)  d_in[0];
    const int*   edge_idx  = (const int*)  d_in[1];
    const float* emb       = (const float*)d_in[2];
    const float* W1        = (const float*)d_in[3];
    const float* att_src1  = (const float*)d_in[4];
    const float* att_dst1  = (const float*)d_in[5];
    const float* b1        = (const float*)d_in[6];
    const float* W2        = (const float*)d_in[7];
    const float* att_src2  = (const float*)d_in[8];
    const float* att_dst2  = (const float*)d_in[9];
    const float* b2        = (const float*)d_in[10];
    const float* gW1       = (const float*)d_in[11];
    const float* gb1       = (const float*)d_in[12];
    const float* gW2       = (const float*)d_in[13];
    const float* gb2       = (const float*)d_in[14];
    float* out = (float*)d_out;

    int n = in_sizes[0];
    int E = in_sizes[1] / 2;
    int ET = E + n;

    float* h1 = nullptr; float* x2 = nullptr; float* h2 = nullptr;
    cudaGetSymbolAddress((void**)&h1, g_h1);
    cudaGetSymbolAddress((void**)&x2, g_x2);
    cudaGetSymbolAddress((void**)&h2, g_h2);

    int warpBlocks = (n * 32 + 255) / 256;

    // init + CSR build
    k_init<<<(n + 255) / 256, 256>>>(n);
    k_count<<<(ET + 255) / 256, 256>>>(edge_idx, E, n);
    k_scan<<<1, 1024>>>(n);
    k_fill<<<(ET + 255) / 256, 256>>>(edge_idx, E, n);

    // layer 1
    dim3 g1((n + BM - 1) / BM, C1 / BN);
    k_gemm<<<g1, 256>>>(nullptr, W1, h1, n, DIM, C1, node_idxs, emb);
    k_alpha1<<<warpBlocks, 256>>>(h1, att_src1, att_dst1, n);
    k_agg1<<<warpBlocks, 256>>>(h1, b1, n);

    // layer 2
    dim3 g2((n + BM - 1) / BM, 1);
    k_gemm<<<g2, 256>>>(x2, W2, h2, n, C1, DHID, nullptr, nullptr);
    k_alpha2<<<warpBlocks, 256>>>(h2, att_src2, att_dst2, n);
    k_agg2<<<warpBlocks, 256>>>(h2, b2, n);

    // gate + pooling
    k_gate<<<(n + 7) / 8, 256>>>(gW1, gb1, gW2, gb2, n);
    k_gmax<<<1, 1024>>>(n);
    k_weights<<<(n + 255) / 256, 256>>>(n);
    k_pool<<<DHID, 256>>>(out, n);
}

// round 2
// speedup vs baseline: 1.1886x; 1.1886x over previous
#include <cuda_runtime.h>
#include <cuda_bf16.h>
#include <math.h>

// Problem constants (fixed-shape problem)
#define DHID    64
#define HEADS   4
#define C1      256      // HEADS*DHID
#define DIM     128      // emb dim
#define SLOPE   0.2f

#define MAXN    20480
#define MAXET   345088   // E + N with margin (320000+20000)

// ---------------- scratch (static device globals; no allocation) ------------
__device__ float g_h1[MAXN * C1];      // layer1 pre-activation features
__device__ float g_x2[MAXN * C1];      // layer1 output (elu)
__device__ float g_h2[MAXN * DHID];    // layer2 pre-agg features
__device__ float g_x3[MAXN * DHID];    // layer2 output (elu)
__device__ float g_asrc1[MAXN * HEADS];
__device__ float g_adst1[MAXN * HEADS];
__device__ float g_asrc2[MAXN];
__device__ float g_adst2[MAXN];
__device__ int   g_deg[MAXN];
__device__ int   g_cursor[MAXN];
__device__ int   g_rowstart[MAXN + 1];
__device__ int   g_srcs[MAXET];
__device__ float g_gate[MAXN];
__device__ unsigned g_gmax_enc;

__device__ __forceinline__ unsigned enc_f(float f) {
    unsigned b = __float_as_uint(f);
    return (b & 0x80000000u) ? ~b : (b | 0x80000000u);
}
__device__ __forceinline__ float dec_f(unsigned e) {
    unsigned b = (e & 0x80000000u) ? (e ^ 0x80000000u) : ~e;
    return __uint_as_float(b);
}

// ---------------- init ----------------
__global__ void k_init(int n) {
    int i = blockIdx.x * blockDim.x + threadIdx.x;
    if (i < n) { g_deg[i] = 0; g_cursor[i] = 0; }
    if (i == 0) { g_gmax_enc = 0u; }
}

// ---------------- CSR build ----------------
__global__ void k_count(const int* __restrict__ ei, int E, int n) {
    int i = blockIdx.x * blockDim.x + threadIdx.x;
    int ET = E + n;
    if (i >= ET) return;
    int dst = (i < E) ? ei[E + i] : (i - E);
    atomicAdd(&g_deg[dst], 1);
}

__global__ void k_scan(int n) {
    __shared__ int ps[1024];
    int tid = threadIdx.x;
    int chunk = (n + 1023) / 1024;
    int s0 = tid * chunk, s1 = min(s0 + chunk, n);
    int sum = 0;
    for (int i = s0; i < s1; i++) sum += g_deg[i];
    ps[tid] = sum;
    __syncthreads();
    if (tid == 0) {
        int run = 0;
        for (int i = 0; i < 1024; i++) { int t = ps[i]; ps[i] = run; run += t; }
        g_rowstart[n] = run;
    }
    __syncthreads();
    int run = ps[tid];
    for (int i = s0; i < s1; i++) { g_rowstart[i] = run; run += g_deg[i]; }
}

__global__ void k_fill(const int* __restrict__ ei, int E, int n) {
    int i = blockIdx.x * blockDim.x + threadIdx.x;
    int ET = E + n;
    if (i >= ET) return;
    int src, dst;
    if (i < E) { src = ei[i]; dst = ei[E + i]; } else { src = dst = i - E; }
    int p = atomicAdd(&g_cursor[dst], 1);
    g_srcs[g_rowstart[dst] + p] = src;
}

// ---------------- tiled SGEMM with optional row-gather + fused alpha --------
// C[M,Ncols] = A[M,K] @ B[K,Ncols]; ridx!=null -> A row m = emb[ridx[m]*K ..]
// If asrc_out != null: BN==64 column block == one head; fused computation of
// alpha_src[r,head] = sum_c h[r,c]*att_src[c], same for dst.
#define BM 128
#define BN 64
#define BK 16
__global__ __launch_bounds__(256) void k_gemm(
    const float* __restrict__ A, const float* __restrict__ B, float* __restrict__ C,
    int M, int K, int Ncols, const int* __restrict__ ridx, const float* __restrict__ emb,
    const float* __restrict__ att_src, const float* __restrict__ att_dst,
    float* __restrict__ asrc_out, float* __restrict__ adst_out, int heads)
{
    __shared__ float As[BK][BM];
    __shared__ float Bs[BK][BN];
    __shared__ int   rs[BM];
    int row0 = blockIdx.x * BM;
    int col0 = blockIdx.y * BN;
    int tid = threadIdx.x;
    int tx = tid & 15, ty = tid >> 4;

    if (ridx) {
        if (tid < BM) {
            int r = row0 + tid;
            rs[tid] = (r < M) ? ridx[r] * K : 0;
        }
    }
    float acc[8][4] = {};
    __syncthreads();

    for (int k0 = 0; k0 < K; k0 += BK) {
        // load A tile: 128 rows x 16 k = 512 float4, 2 per thread
        #pragma unroll
        for (int t = 0; t < 2; t++) {
            int vid = tid * 2 + t;
            int m = vid >> 2;        // 0..127
            int kq = (vid & 3) * 4;  // 0,4,8,12
            int gr = row0 + m;
            float4 v = make_float4(0.f, 0.f, 0.f, 0.f);
            if (gr < M) {
                const float* Arow = ridx ? (emb + rs[m]) : (A + (size_t)gr * K);
                v = *(const float4*)(Arow + k0 + kq);
            }
            As[kq + 0][m] = v.x;
            As[kq + 1][m] = v.y;
            As[kq + 2][m] = v.z;
            As[kq + 3][m] = v.w;
        }
        // load B tile: 16 rows x 64 cols = 256 float4, 1 per thread
        {
            int k = tid >> 4;
            int c = (tid & 15) * 4;
            float4 v = *(const float4*)(B + (size_t)(k0 + k) * Ncols + col0 + c);
            *(float4*)&Bs[k][c] = v;
        }
        __syncthreads();
        #pragma unroll
        for (int k = 0; k < BK; k++) {
            float4 a0 = *(const float4*)&As[k][ty * 8];
            float4 a1 = *(const float4*)&As[k][ty * 8 + 4];
            float4 b  = *(const float4*)&Bs[k][tx * 4];
            float a[8] = {a0.x, a0.y, a0.z, a0.w, a1.x, a1.y, a1.z, a1.w};
            float bb[4] = {b.x, b.y, b.z, b.w};
            #pragma unroll
            for (int i = 0; i < 8; i++)
                #pragma unroll
                for (int j = 0; j < 4; j++) acc[i][j] += a[i] * bb[j];
        }
        __syncthreads();
    }

    // store C
    #pragma unroll
    for (int i = 0; i < 8; i++) {
        int r = row0 + ty * 8 + i;
        if (r < M) {
            float4 v = make_float4(acc[i][0], acc[i][1], acc[i][2], acc[i][3]);
            *(float4*)(C + (size_t)r * Ncols + col0 + tx * 4) = v;
        }
    }

    // fused alpha: dot over this block's 64 columns (one head)
    if (asrc_out) {
        int head = col0 >> 6;
        float as[4], ad[4];
        #pragma unroll
        for (int j = 0; j < 4; j++) {
            as[j] = att_src[col0 + tx * 4 + j];
            ad[j] = att_dst[col0 + tx * 4 + j];
        }
        #pragma unroll
        for (int i = 0; i < 8; i++) {
            float ps = acc[i][0] * as[0] + acc[i][1] * as[1] + acc[i][2] * as[2] + acc[i][3] * as[3];
            float pd = acc[i][0] * ad[0] + acc[i][1] * ad[1] + acc[i][2] * ad[2] + acc[i][3] * ad[3];
            #pragma unroll
            for (int o = 8; o; o >>= 1) {
                ps += __shfl_xor_sync(0xFFFFFFFFu, ps, o);
                pd += __shfl_xor_sync(0xFFFFFFFFu, pd, o);
            }
            if (tx == 0) {
                int r = row0 + ty * 8 + i;
                if (r < M) {
                    asrc_out[r * heads + head] = ps;
                    adst_out[r * heads + head] = pd;
                }
            }
        }
    }
}

// ---------------- layer1 aggregation: warp per dst node ----------------
__global__ __launch_bounds__(256) void k_agg1(
    const float* __restrict__ h1, const float* __restrict__ b1, int n)
{
    int gw = (blockIdx.x * blockDim.x + threadIdx.x) >> 5;
    int lane = threadIdx.x & 31;
    if (gw >= n) return;
    int head = lane >> 3;
    int s0 = g_rowstart[gw], s1 = g_rowstart[gw + 1];
    float adst_n = g_adst1[gw * HEADS + head];
    float m = -1e30f;
    for (int e = s0; e < s1; e++) {
        int src = g_srcs[e];
        float l = g_asrc1[src * HEADS + head] + adst_n;
        l = l > 0.f ? l : SLOPE * l;
        m = fmaxf(m, l);
    }
    float acc[8] = {0, 0, 0, 0, 0, 0, 0, 0};
    float se = 0.f;
    for (int e = s0; e < s1; e++) {
        int src = g_srcs[e];
        float l = g_asrc1[src * HEADS + head] + adst_n;
        l = l > 0.f ? l : SLOPE * l;
        float p = __expf(l - m);
        se += p;
        const float4* hp = (const float4*)(h1 + (size_t)src * C1 + lane * 8);
        float4 v0 = hp[0], v1 = hp[1];
        acc[0] += p * v0.x; acc[1] += p * v0.y; acc[2] += p * v0.z; acc[3] += p * v0.w;
        acc[4] += p * v1.x; acc[5] += p * v1.y; acc[6] += p * v1.z; acc[7] += p * v1.w;
    }
    float inv = 1.f / se;
    #pragma unroll
    for (int j = 0; j < 8; j++) {
        int c = lane * 8 + j;
        float v = acc[j] * inv + b1[c];
        g_x2[(size_t)gw * C1 + c] = v > 0.f ? v : expm1f(v);
    }
}

// ---------------- layer2 aggregation ----------------
__global__ __launch_bounds__(256) void k_agg2(
    const float* __restrict__ h2, const float* __restrict__ b2, int n)
{
    int gw = (blockIdx.x * blockDim.x + threadIdx.x) >> 5;
    int lane = threadIdx.x & 31;
    if (gw >= n) return;
    int s0 = g_rowstart[gw], s1 = g_rowstart[gw + 1];
    float adst_n = g_adst2[gw];
    float m = -1e30f;
    for (int e = s0; e < s1; e++) {
        int src = g_srcs[e];
        float l = g_asrc2[src] + adst_n;
        l = l > 0.f ? l : SLOPE * l;
        m = fmaxf(m, l);
    }
    float a0 = 0.f, a1 = 0.f, se = 0.f;
    for (int e = s0; e < s1; e++) {
        int src = g_srcs[e];
        float l = g_asrc2[src] + adst_n;
        l = l > 0.f ? l : SLOPE * l;
        float p = __expf(l - m);
        se += p;
        const float2* hp = (const float2*)(h2 + (size_t)src * DHID + lane * 2);
        float2 v = hp[0];
        a0 += p * v.x; a1 += p * v.y;
    }
    float inv = 1.f / se;
    float o0 = a0 * inv + b2[lane * 2];
    float o1 = a1 * inv + b2[lane * 2 + 1];
    g_x3[(size_t)gw * DHID + lane * 2]     = o0 > 0.f ? o0 : expm1f(o0);
    g_x3[(size_t)gw * DHID + lane * 2 + 1] = o1 > 0.f ? o1 : expm1f(o1);
}

// ---------------- gate MLP: warp per node, fused global max ----------------
__global__ __launch_bounds__(256) void k_gate(
    const float* __restrict__ gW1, const float* __restrict__ gb1,
    const float* __restrict__ gW2, const float* __restrict__ gb2, int n)
{
    __shared__ float Ws[DHID * DHID];
    __shared__ float xr[8][DHID];
    __shared__ unsigned bmax;
    int tid = threadIdx.x;
    for (int i = tid; i < DHID * DHID; i += 256) Ws[i] = gW1[i];
    if (tid == 0) bmax = 0u;
    int w = tid >> 5, lane = tid & 31;
    int node = blockIdx.x * 8 + w;
    __syncthreads();
    float gval = -1e30f;
    if (node < n) {
        xr[w][lane]      = g_x3[(size_t)node * DHID + lane];
        xr[w][lane + 32] = g_x3[(size_t)node * DHID + lane + 32];
        __syncwarp();
        float a0 = gb1[lane], a1 = gb1[lane + 32];
        #pragma unroll 8
        for (int k = 0; k < DHID; k++) {
            float xv = xr[w][k];
            a0 += xv * Ws[k * DHID + lane];
            a1 += xv * Ws[k * DHID + lane + 32];
        }
        a0 = fmaxf(a0, 0.f); a1 = fmaxf(a1, 0.f);
        float g = a0 * gW2[lane] + a1 * gW2[lane + 32];
        #pragma unroll
        for (int o = 16; o; o >>= 1) g += __shfl_xor_sync(0xFFFFFFFFu, g, o);
        g += gb2[0];
        if (lane == 0) { g_gate[node] = g; gval = g; }
    }
    // block-level max then one global atomic
    if (lane == 0 && node < n) atomicMax(&bmax, enc_f(gval));
    __syncthreads();
    if (tid == 0) atomicMax(&g_gmax_enc, bmax);
}

// ---------------- final pool: one block per channel, self-normalizing ------
__global__ void k_pool(float* __restrict__ out, int n) {
    __shared__ float red[256];
    __shared__ float redw[256];
    int c = blockIdx.x;
    int tid = threadIdx.x;
    float gmax = dec_f(g_gmax_enc);
    float s = 0.f, sw = 0.f;
    for (int i = tid; i < n; i += 256) {
        float w = __expf(g_gate[i] - gmax);
        s += w * g_x3[(size_t)i * DHID + c];
        sw += w;
    }
    red[tid] = s; redw[tid] = sw;
    __syncthreads();
    for (int o = 128; o; o >>= 1) {
        if (tid < o) { red[tid] += red[tid + o]; redw[tid] += redw[tid + o]; }
        __syncthreads();
    }
    if (tid == 0) out[c] = red[0] / redw[0];
}

// ---------------- launch ----------------
extern "C" void kernel_launch(void* const* d_in, const int* in_sizes, int n_in,
                              void* d_out, int out_size) {
    const int*   node_idxs = (const int*)  d_in[0];
    const int*   edge_idx  = (const int*)  d_in[1];
    const float* emb       = (const float*)d_in[2];
    const float* W1        = (const float*)d_in[3];
    const float* att_src1  = (const float*)d_in[4];
    const float* att_dst1  = (const float*)d_in[5];
    const float* b1        = (const float*)d_in[6];
    const float* W2        = (const float*)d_in[7];
    const float* att_src2  = (const float*)d_in[8];
    const float* att_dst2  = (const float*)d_in[9];
    const float* b2        = (const float*)d_in[10];
    const float* gW1       = (const float*)d_in[11];
    const float* gb1       = (const float*)d_in[12];
    const float* gW2       = (const float*)d_in[13];
    const float* gb2       = (const float*)d_in[14];
    float* out = (float*)d_out;

    int n = in_sizes[0];
    int E = in_sizes[1] / 2;
    int ET = E + n;

    float* h1 = nullptr; float* x2 = nullptr; float* h2 = nullptr;
    float* as1 = nullptr; float* ad1 = nullptr; float* as2 = nullptr; float* ad2 = nullptr;
    cudaGetSymbolAddress((void**)&h1, g_h1);
    cudaGetSymbolAddress((void**)&x2, g_x2);
    cudaGetSymbolAddress((void**)&h2, g_h2);
    cudaGetSymbolAddress((void**)&as1, g_asrc1);
    cudaGetSymbolAddress((void**)&ad1, g_adst1);
    cudaGetSymbolAddress((void**)&as2, g_asrc2);
    cudaGetSymbolAddress((void**)&ad2, g_adst2);

    int warpBlocks = (n * 32 + 255) / 256;

    // init + CSR build
    k_init<<<(n + 255) / 256, 256>>>(n);
    k_count<<<(ET + 255) / 256, 256>>>(edge_idx, E, n);
    k_scan<<<1, 1024>>>(n);
    k_fill<<<(ET + 255) / 256, 256>>>(edge_idx, E, n);

    // layer 1: gathered GEMM + fused alpha
    dim3 g1((n + BM - 1) / BM, C1 / BN);
    k_gemm<<<g1, 256>>>(nullptr, W1, h1, n, DIM, C1, node_idxs, emb,
                        att_src1, att_dst1, as1, ad1, HEADS);
    k_agg1<<<warpBlocks, 256>>>(h1, b1, n);

    // layer 2: GEMM + fused alpha
    dim3 g2((n + BM - 1) / BM, 1);
    k_gemm<<<g2, 256>>>(x2, W2, h2, n, C1, DHID, nullptr, nullptr,
                        att_src2, att_dst2, as2, ad2, 1);
    k_agg2<<<warpBlocks, 256>>>(h2, b2, n);

    // gate (+global max) + pool (self-normalizing)
    k_gate<<<(n + 7) / 8, 256>>>(gW1, gb1, gW2, gb2, n);
    k_pool<<<DHID, 256>>>(out, n);
}

// round 3
// speedup vs baseline: 1.5583x; 1.3110x over previous
#include <cuda_runtime.h>
#include <cuda_fp16.h>
#include <math.h>

// Problem constants (fixed-shape problem)
#define DHID    64
#define HEADS   4
#define C1      256      // HEADS*DHID
#define DIM     128      // emb dim
#define SLOPE   0.2f

#define MAXN    20480
#define MAXET   345088   // E + N with margin (320000+20000)

// ---------------- scratch (static device globals; no allocation) ------------
__device__ __half g_h1[MAXN * C1];     // layer1 pre-activation features (fp16)
__device__ float  g_x2[MAXN * C1];     // layer1 output (elu)
__device__ __half g_h2[MAXN * DHID];   // layer2 pre-agg features (fp16)
__device__ float  g_x3[MAXN * DHID];   // layer2 output (elu)
__device__ float  g_asrc1[MAXN * HEADS];
__device__ float  g_adst1[MAXN * HEADS];
__device__ float  g_asrc2[MAXN];
__device__ float  g_adst2[MAXN];
__device__ int    g_deg[MAXN];         // zero-initialized; re-zeroed by k_pool
__device__ int    g_cursor[MAXN];      // zero-initialized; re-zeroed by k_pool
__device__ int    g_rowstart[MAXN + 1];
__device__ int    g_srcs[MAXET];
__device__ float  g_gate[MAXN];
__device__ unsigned g_gmax_enc;        // zeroed in k_scan each run

__device__ __forceinline__ unsigned enc_f(float f) {
    unsigned b = __float_as_uint(f);
    return (b & 0x80000000u) ? ~b : (b | 0x80000000u);
}
__device__ __forceinline__ float dec_f(unsigned e) {
    unsigned b = (e & 0x80000000u) ? (e ^ 0x80000000u) : ~e;
    return __uint_as_float(b);
}

// ---------------- CSR build ----------------
__global__ void k_count(const int* __restrict__ ei, int E, int n) {
    int i = blockIdx.x * blockDim.x + threadIdx.x;
    int ET = E + n;
    if (i >= ET) return;
    int dst = (i < E) ? ei[E + i] : (i - E);
    atomicAdd(&g_deg[dst], 1);
}

__global__ void k_scan(int n) {
    __shared__ int ps[1024];
    int tid = threadIdx.x;
    if (tid == 0) g_gmax_enc = 0u;
    int chunk = (n + 1023) / 1024;
    int s0 = tid * chunk, s1 = min(s0 + chunk, n);
    int sum = 0;
    for (int i = s0; i < s1; i++) sum += g_deg[i];
    ps[tid] = sum;
    __syncthreads();
    if (tid == 0) {
        int run = 0;
        for (int i = 0; i < 1024; i++) { int t = ps[i]; ps[i] = run; run += t; }
        g_rowstart[n] = run;
    }
    __syncthreads();
    int run = ps[tid];
    for (int i = s0; i < s1; i++) { g_rowstart[i] = run; run += g_deg[i]; }
}

__global__ void k_fill(const int* __restrict__ ei, int E, int n) {
    int i = blockIdx.x * blockDim.x + threadIdx.x;
    int ET = E + n;
    if (i >= ET) return;
    int src, dst;
    if (i < E) { src = ei[i]; dst = ei[E + i]; } else { src = dst = i - E; }
    int p = atomicAdd(&g_cursor[dst], 1);
    g_srcs[g_rowstart[dst] + p] = src;
}

// ---------------- tf32 tensor-core GEMM + fused alpha epilogue ----------------
// C[M,Ncols] = A[M,K] @ B[K,Ncols], C stored as fp16.
// ridx != null -> A row m = emb[ridx[m]*K ..]
// Fused: alpha_src[r,head] = sum over this 64-col block of h*att_src (block = one head).
#define BM 128
#define BN 64
#define BK 32

__device__ __forceinline__ float to_tf32(float x) {
    unsigned u; asm("cvt.rna.tf32.f32 %0, %1;" : "=r"(u) : "f"(x));
    return __uint_as_float(u);
}

__device__ __forceinline__ void mma8(float* d, const float* a, const float* b) {
    asm volatile(
        "mma.sync.aligned.m16n8k8.row.col.f32.tf32.tf32.f32 "
        "{%0,%1,%2,%3}, {%4,%5,%6,%7}, {%8,%9}, {%0,%1,%2,%3};"
        : "+f"(d[0]), "+f"(d[1]), "+f"(d[2]), "+f"(d[3])
        : "r"(__float_as_uint(a[0])), "r"(__float_as_uint(a[1])),
          "r"(__float_as_uint(a[2])), "r"(__float_as_uint(a[3])),
          "r"(__float_as_uint(b[0])), "r"(__float_as_uint(b[1])));
}

__global__ __launch_bounds__(256) void k_gemm_tc(
    const float* __restrict__ A, const float* __restrict__ B, __half* __restrict__ Cout,
    int M, int K, int Ncols, const int* __restrict__ ridx, const float* __restrict__ emb,
    const float* __restrict__ att_src, const float* __restrict__ att_dst,
    float* __restrict__ asrc_out, float* __restrict__ adst_out, int heads)
{
    __shared__ float As[BM][36];   // pad -> conflict-free frag loads (4m+k distinct)
    __shared__ float Bs[BK][72];   // pad -> conflict-free frag loads (8k+n distinct)
    __shared__ int rs[BM];
    int tid = threadIdx.x;
    int row0 = blockIdx.x * BM;
    int col0 = blockIdx.y * BN;
    int wid = tid >> 5, lane = tid & 31;
    int g = lane >> 2, tig = lane & 3;

    if (ridx && tid < BM) {
        int r = row0 + tid;
        rs[tid] = (r < M) ? ridx[r] * K : 0;
    }
    float acc[8][4] = {};   // 8 n-tiles (n8) x 4 accum regs; warp tile 16x64
    __syncthreads();

    for (int k0 = 0; k0 < K; k0 += BK) {
        // A tile 128x32: 1024 float4, 4 per thread
        #pragma unroll
        for (int t = 0; t < 4; t++) {
            int vid = tid + 256 * t;
            int m = vid >> 3, kq = (vid & 7) * 4;
            int gr = row0 + m;
            float4 v = make_float4(0.f, 0.f, 0.f, 0.f);
            if (gr < M) {
                const float* Ar = ridx ? (emb + rs[m]) : (A + (size_t)gr * K);
                v = *(const float4*)(Ar + k0 + kq);
            }
            As[m][kq + 0] = to_tf32(v.x);
            As[m][kq + 1] = to_tf32(v.y);
            As[m][kq + 2] = to_tf32(v.z);
            As[m][kq + 3] = to_tf32(v.w);
        }
        // B tile 32x64: 512 float4, 2 per thread
        #pragma unroll
        for (int t = 0; t < 2; t++) {
            int vid = tid + 256 * t;
            int k = vid >> 4, nq = (vid & 15) * 4;
            float4 v = *(const float4*)(B + (size_t)(k0 + k) * Ncols + col0 + nq);
            Bs[k][nq + 0] = to_tf32(v.x);
            Bs[k][nq + 1] = to_tf32(v.y);
            Bs[k][nq + 2] = to_tf32(v.z);
            Bs[k][nq + 3] = to_tf32(v.w);
        }
        __syncthreads();
        int mt = wid * 16;
        #pragma unroll
        for (int kk = 0; kk < 4; kk++) {
            int kb = kk * 8;
            float a[4];
            a[0] = As[mt + g][kb + tig];
            a[1] = As[mt + g + 8][kb + tig];
            a[2] = As[mt + g][kb + tig + 4];
            a[3] = As[mt + g + 8][kb + tig + 4];
            #pragma unroll
            for (int j = 0; j < 8; j++) {
                float b[2];
                b[0] = Bs[kb + tig][j * 8 + g];
                b[1] = Bs[kb + tig + 4][j * 8 + g];
                mma8(acc[j], a, b);
            }
        }
        __syncthreads();
    }

    // store C (fp16)
    int r0 = row0 + wid * 16 + g;
    int r1 = r0 + 8;
    #pragma unroll
    for (int j = 0; j < 8; j++) {
        int c = col0 + j * 8 + tig * 2;
        if (r0 < M) *(__half2*)(Cout + (size_t)r0 * Ncols + c) = __floats2half2_rn(acc[j][0], acc[j][1]);
        if (r1 < M) *(__half2*)(Cout + (size_t)r1 * Ncols + c) = __floats2half2_rn(acc[j][2], acc[j][3]);
    }

    // fused alpha over this block's 64 cols (= one head); fp32 accum
    if (asrc_out) {
        int head = blockIdx.y;
        float s0 = 0.f, d0 = 0.f, s1 = 0.f, d1 = 0.f;
        #pragma unroll
        for (int j = 0; j < 8; j++) {
            int c = col0 + j * 8 + tig * 2;
            float w0 = att_src[c], w1 = att_src[c + 1];
            float v0 = att_dst[c], v1 = att_dst[c + 1];
            s0 += acc[j][0] * w0 + acc[j][1] * w1;
            d0 += acc[j][0] * v0 + acc[j][1] * v1;
            s1 += acc[j][2] * w0 + acc[j][3] * w1;
            d1 += acc[j][2] * v0 + acc[j][3] * v1;
        }
        #pragma unroll
        for (int o = 1; o <= 2; o <<= 1) {
            s0 += __shfl_xor_sync(0xFFFFFFFFu, s0, o);
            d0 += __shfl_xor_sync(0xFFFFFFFFu, d0, o);
            s1 += __shfl_xor_sync(0xFFFFFFFFu, s1, o);
            d1 += __shfl_xor_sync(0xFFFFFFFFu, d1, o);
        }
        if (tig == 0) {
            if (r0 < M) { asrc_out[r0 * heads + head] = s0; adst_out[r0 * heads + head] = d0; }
            if (r1 < M) { asrc_out[r1 * heads + head] = s1; adst_out[r1 * heads + head] = d1; }
        }
    }
}

// ---------------- layer1 aggregation: warp per dst node (fp16 gather) -------
__global__ __launch_bounds__(256) void k_agg1(
    const __half* __restrict__ h1, const float* __restrict__ b1, int n)
{
    int gw = (blockIdx.x * blockDim.x + threadIdx.x) >> 5;
    int lane = threadIdx.x & 31;
    if (gw >= n) return;
    int head = lane >> 3;
    int s0 = g_rowstart[gw], s1 = g_rowstart[gw + 1];
    float adst_n = g_adst1[gw * HEADS + head];
    float m = -1e30f;
    for (int e = s0; e < s1; e++) {
        int src = g_srcs[e];
        float l = g_asrc1[src * HEADS + head] + adst_n;
        l = l > 0.f ? l : SLOPE * l;
        m = fmaxf(m, l);
    }
    float acc[8] = {0, 0, 0, 0, 0, 0, 0, 0};
    float se = 0.f;
    for (int e = s0; e < s1; e++) {
        int src = g_srcs[e];
        float l = g_asrc1[src * HEADS + head] + adst_n;
        l = l > 0.f ? l : SLOPE * l;
        float p = __expf(l - m);
        se += p;
        int4 q = *(const int4*)(h1 + (size_t)src * C1 + lane * 8);  // 8 halves
        float2 f0 = __half22float2(*(__half2*)&q.x);
        float2 f1 = __half22float2(*(__half2*)&q.y);
        float2 f2 = __half22float2(*(__half2*)&q.z);
        float2 f3 = __half22float2(*(__half2*)&q.w);
        acc[0] += p * f0.x; acc[1] += p * f0.y;
        acc[2] += p * f1.x; acc[3] += p * f1.y;
        acc[4] += p * f2.x; acc[5] += p * f2.y;
        acc[6] += p * f3.x; acc[7] += p * f3.y;
    }
    float inv = 1.f / se;
    #pragma unroll
    for (int j = 0; j < 8; j++) {
        int c = lane * 8 + j;
        float v = acc[j] * inv + b1[c];
        g_x2[(size_t)gw * C1 + c] = v > 0.f ? v : expm1f(v);
    }
}

// ---------------- layer2 aggregation fused with gate MLP + global max -------
__global__ __launch_bounds__(256) void k_agg2gate(
    const __half* __restrict__ h2, const float* __restrict__ b2,
    const float* __restrict__ gW1, const float* __restrict__ gb1,
    const float* __restrict__ gW2, const float* __restrict__ gb2, int n)
{
    __shared__ float Ws[DHID * DHID];
    __shared__ float xr[8][DHID];
    __shared__ unsigned bmax;
    int tid = threadIdx.x;
    for (int i = tid; i < DHID * DHID; i += 256) Ws[i] = gW1[i];
    if (tid == 0) bmax = 0u;
    int w = tid >> 5, lane = tid & 31;
    int node = blockIdx.x * 8 + w;
    if (node < n) {
        int s0 = g_rowstart[node], s1 = g_rowstart[node + 1];
        float adst_n = g_adst2[node];
        float m = -1e30f;
        for (int e = s0; e < s1; e++) {
            int src = g_srcs[e];
            float l = g_asrc2[src] + adst_n;
            l = l > 0.f ? l : SLOPE * l;
            m = fmaxf(m, l);
        }
        float a0 = 0.f, a1 = 0.f, se = 0.f;
        for (int e = s0; e < s1; e++) {
            int src = g_srcs[e];
            float l = g_asrc2[src] + adst_n;
            l = l > 0.f ? l : SLOPE * l;
            float p = __expf(l - m);
            se += p;
            float2 f = __half22float2(*(const __half2*)(h2 + (size_t)src * DHID + lane * 2));
            a0 += p * f.x; a1 += p * f.y;
        }
        float inv = 1.f / se;
        float o0 = a0 * inv + b2[lane * 2];
        float o1 = a1 * inv + b2[lane * 2 + 1];
        o0 = o0 > 0.f ? o0 : expm1f(o0);
        o1 = o1 > 0.f ? o1 : expm1f(o1);
        g_x3[(size_t)node * DHID + lane * 2]     = o0;
        g_x3[(size_t)node * DHID + lane * 2 + 1] = o1;
        xr[w][lane * 2] = o0; xr[w][lane * 2 + 1] = o1;
    }
    __syncthreads();  // Ws + xr ready
    if (node < n) {
        float a0 = gb1[lane], a1 = gb1[lane + 32];
        #pragma unroll 8
        for (int k = 0; k < DHID; k++) {
            float xv = xr[w][k];
            a0 += xv * Ws[k * DHID + lane];
            a1 += xv * Ws[k * DHID + lane + 32];
        }
        a0 = fmaxf(a0, 0.f); a1 = fmaxf(a1, 0.f);
        float gv = a0 * gW2[lane] + a1 * gW2[lane + 32];
        #pragma unroll
        for (int o = 16; o; o >>= 1) gv += __shfl_xor_sync(0xFFFFFFFFu, gv, o);
        if (lane == 0) {
            gv += gb2[0];
            g_gate[node] = gv;
            atomicMax(&bmax, enc_f(gv));
        }
    }
    __syncthreads();
    if (tid == 0) atomicMax(&g_gmax_enc, bmax);
}

// ---------------- final pool: one block per channel, self-normalizing -------
// Also re-zeroes deg/cursor for the next graph replay.
__global__ void k_pool(float* __restrict__ out, int n) {
    int gt = blockIdx.x * 256 + threadIdx.x;
    for (int i = gt; i < n; i += DHID * 256) { g_deg[i] = 0; g_cursor[i] = 0; }

    __shared__ float red[256];
    __shared__ float redw[256];
    int c = blockIdx.x;
    int tid = threadIdx.x;
    float gmax = dec_f(g_gmax_enc);
    float s = 0.f, sw = 0.f;
    for (int i = tid; i < n; i += 256) {
        float w = __expf(g_gate[i] - gmax);
        s += w * g_x3[(size_t)i * DHID + c];
        sw += w;
    }
    red[tid] = s; redw[tid] = sw;
    __syncthreads();
    for (int o = 128; o; o >>= 1) {
        if (tid < o) { red[tid] += red[tid + o]; redw[tid] += redw[tid + o]; }
        __syncthreads();
    }
    if (tid == 0) out[c] = red[0] / redw[0];
}

// ---------------- launch ----------------
extern "C" void kernel_launch(void* const* d_in, const int* in_sizes, int n_in,
                              void* d_out, int out_size) {
    const int*   node_idxs = (const int*)  d_in[0];
    const int*   edge_idx  = (const int*)  d_in[1];
    const float* emb       = (const float*)d_in[2];
    const float* W1        = (const float*)d_in[3];
    const float* att_src1  = (const float*)d_in[4];
    const float* att_dst1  = (const float*)d_in[5];
    const float* b1        = (const float*)d_in[6];
    const float* W2        = (const float*)d_in[7];
    const float* att_src2  = (const float*)d_in[8];
    const float* att_dst2  = (const float*)d_in[9];
    const float* b2        = (const float*)d_in[10];
    const float* gW1       = (const float*)d_in[11];
    const float* gb1       = (const float*)d_in[12];
    const float* gW2       = (const float*)d_in[13];
    const float* gb2       = (const float*)d_in[14];
    float* out = (float*)d_out;

    int n = in_sizes[0];
    int E = in_sizes[1] / 2;
    int ET = E + n;

    __half* h1 = nullptr; float* x2 = nullptr; __half* h2 = nullptr;
    float* as1 = nullptr; float* ad1 = nullptr; float* as2 = nullptr; float* ad2 = nullptr;
    cudaGetSymbolAddress((void**)&h1, g_h1);
    cudaGetSymbolAddress((void**)&x2, g_x2);
    cudaGetSymbolAddress((void**)&h2, g_h2);
    cudaGetSymbolAddress((void**)&as1, g_asrc1);
    cudaGetSymbolAddress((void**)&ad1, g_adst1);
    cudaGetSymbolAddress((void**)&as2, g_asrc2);
    cudaGetSymbolAddress((void**)&ad2, g_adst2);

    int warpBlocks = (n * 32 + 255) / 256;

    // CSR build (deg/cursor zeroed by k_pool of previous run; statics start zeroed)
    k_count<<<(ET + 255) / 256, 256>>>(edge_idx, E, n);
    k_scan<<<1, 1024>>>(n);
    k_fill<<<(ET + 255) / 256, 256>>>(edge_idx, E, n);

    // layer 1: gathered tf32 GEMM + fused alpha
    dim3 g1((n + BM - 1) / BM, C1 / BN);
    k_gemm_tc<<<g1, 256>>>(nullptr, W1, h1, n, DIM, C1, node_idxs, emb,
                           att_src1, att_dst1, as1, ad1, HEADS);
    k_agg1<<<warpBlocks, 256>>>(h1, b1, n);

    // layer 2: tf32 GEMM + fused alpha
    dim3 g2((n + BM - 1) / BM, 1);
    k_gemm_tc<<<g2, 256>>>(x2, W2, h2, n, C1, DHID, nullptr, nullptr,
                           att_src2, att_dst2, as2, ad2, 1);
    k_agg2gate<<<(n + 7) / 8, 256>>>(h2, b2, gW1, gb1, gW2, gb2, n);

    // pool (self-normalizing softmax over gate)
    k_pool<<<DHID, 256>>>(out, n);
}

// round 4
// speedup vs baseline: 1.6897x; 1.0843x over previous
#include <cuda_runtime.h>
#include <cuda_fp16.h>
#include <math.h>

#define DHID    64
#define HEADS   4
#define C1      256
#define DIM     128
#define SLOPE   0.2f

#define MAXN    20480
#define MAXET   345088

// ---------------- scratch ----------------
__device__ __half g_h1[MAXN * C1];
__device__ __half g_x2[MAXN * C1];     // layer1 output (elu), fp16
__device__ __half g_h2[MAXN * DHID];
__device__ float  g_x3[MAXN * DHID];
__device__ float  g_asrc1[MAXN * HEADS];
__device__ float  g_adst1[MAXN * HEADS];
__device__ float  g_asrc2[MAXN];
__device__ float  g_adst2[MAXN];
__device__ int    g_deg[MAXN];         // zeroed initially; re-zeroed by k_pool
__device__ int    g_cursor[MAXN];      // seeded by k_scan each run
__device__ int    g_rowstart[MAXN + 1];
__device__ int    g_srcs[MAXET];
__device__ float  g_gate[MAXN];
__device__ unsigned g_gmax_enc;
__device__ __half g_W1t[C1 * DIM];     // W1^T  [n=256][k=128] fp16
__device__ __half g_W2t[DHID * C1];    // W2^T  [n=64][k=256] fp16

__device__ __forceinline__ unsigned enc_f(float f) {
    unsigned b = __float_as_uint(f);
    return (b & 0x80000000u) ? ~b : (b | 0x80000000u);
}
__device__ __forceinline__ float dec_f(unsigned e) {
    unsigned b = (e & 0x80000000u) ? (e ^ 0x80000000u) : ~e;
    return __uint_as_float(b);
}

// ---------------- weight transpose+convert (tiny) ----------------
__global__ void k_prepw(const float* __restrict__ W1, const float* __restrict__ W2) {
    int t = blockIdx.x * blockDim.x + threadIdx.x;
    // W1: [128][256] -> W1t [256][128]
    for (int i = t; i < DIM * C1; i += gridDim.x * blockDim.x) {
        int k = i / C1, nn = i % C1;
        g_W1t[nn * DIM + k] = __float2half_rn(W1[i]);
    }
    // W2: [256][64] -> W2t [64][256]
    for (int i = t; i < C1 * DHID; i += gridDim.x * blockDim.x) {
        int k = i / DHID, nn = i % DHID;
        g_W2t[nn * C1 + k] = __float2half_rn(W2[i]);
    }
}

// ---------------- CSR build ----------------
__global__ void k_count(const int* __restrict__ ei, int E) {
    int base = (blockIdx.x * blockDim.x + threadIdx.x) * 4;
    if (base + 3 < E) {
        int4 d = *(const int4*)(ei + E + base);
        atomicAdd(&g_deg[d.x], 1);
        atomicAdd(&g_deg[d.y], 1);
        atomicAdd(&g_deg[d.z], 1);
        atomicAdd(&g_deg[d.w], 1);
    } else {
        for (int t = 0; t < 4; t++) {
            int i = base + t;
            if (i < E) atomicAdd(&g_deg[ei[E + i]], 1);
        }
    }
}

__global__ void k_scan(int n) {
    __shared__ int ps[1024];
    int tid = threadIdx.x;
    if (tid == 0) g_gmax_enc = 0u;
    int chunk = (n + 1023) / 1024;
    int s0 = tid * chunk, s1 = min(s0 + chunk, n);
    int sum = 0;
    for (int i = s0; i < s1; i++) sum += g_deg[i] + 1;   // +1 self loop
    ps[tid] = sum;
    __syncthreads();
    if (tid == 0) {
        int run = 0;
        for (int i = 0; i < 1024; i++) { int t = ps[i]; ps[i] = run; run += t; }
        g_rowstart[n] = run;
    }
    __syncthreads();
    int run = ps[tid];
    for (int i = s0; i < s1; i++) {
        g_rowstart[i] = run;
        g_cursor[i] = run;           // seed cursor
        run += g_deg[i] + 1;
    }
}

__global__ void k_fill(const int* __restrict__ ei, int E, int n) {
    int base = (blockIdx.x * blockDim.x + threadIdx.x) * 4;
    int ET = E + n;
    if (base + 3 < E) {
        int4 s = *(const int4*)(ei + base);
        int4 d = *(const int4*)(ei + E + base);
        g_srcs[atomicAdd(&g_cursor[d.x], 1)] = s.x;
        g_srcs[atomicAdd(&g_cursor[d.y], 1)] = s.y;
        g_srcs[atomicAdd(&g_cursor[d.z], 1)] = s.z;
        g_srcs[atomicAdd(&g_cursor[d.w], 1)] = s.w;
    } else {
        for (int t = 0; t < 4; t++) {
            int i = base + t;
            if (i >= ET) break;
            int src, dst;
            if (i < E) { src = ei[i]; dst = ei[E + i]; } else { src = dst = i - E; }
            g_srcs[atomicAdd(&g_cursor[dst], 1)] = src;
        }
    }
}

// ---------------- fp16 tensor-core GEMM + fused alpha epilogue --------------
// C[M,Ncols](fp16) = A[M,K] @ W^T ; A is fp32-gathered (layer1) or fp16 (layer2).
#define BM 128
#define BN 64
#define BKH 64   // k-halves per smem tile

__device__ __forceinline__ void mma16(float* d, const unsigned* a, const unsigned* b) {
    asm("mma.sync.aligned.m16n8k16.row.col.f32.f16.f16.f32 "
        "{%0,%1,%2,%3}, {%4,%5,%6,%7}, {%8,%9}, {%0,%1,%2,%3};"
        : "+f"(d[0]), "+f"(d[1]), "+f"(d[2]), "+f"(d[3])
        : "r"(a[0]), "r"(a[1]), "r"(a[2]), "r"(a[3]), "r"(b[0]), "r"(b[1]));
}

__global__ __launch_bounds__(256) void k_gemm_f16(
    const __half* __restrict__ A16, const __half* __restrict__ Wt,
    __half* __restrict__ Cout, int M, int K, int Ncols,
    const int* __restrict__ ridx, const float* __restrict__ emb,
    const float* __restrict__ att_src, const float* __restrict__ att_dst,
    float* __restrict__ asrc_out, float* __restrict__ adst_out, int heads)
{
    __shared__ __half As[BM][BKH + 8];   // row stride 72 halves = 144B: conflict-free
    __shared__ __half Bs[BN][BKH + 8];
    __shared__ int rs[BM];
    int tid = threadIdx.x;
    int row0 = blockIdx.x * BM;
    int col0 = blockIdx.y * BN;
    int wid = tid >> 5, lane = tid & 31;
    int g = lane >> 2, tig = lane & 3;

    if (ridx && tid < BM) {
        int r = row0 + tid;
        rs[tid] = (r < M) ? ridx[r] * K : 0;
    }
    float acc[8][4] = {};
    __syncthreads();

    for (int k0 = 0; k0 < K; k0 += BKH) {
        // ---- A tile 128 x 64 halves ----
        if (ridx) {
            // gathered fp32 -> fp16: 8192 floats, 32/thread
            #pragma unroll
            for (int t = 0; t < 4; t++) {
                int vid = tid + 256 * t;
                int m = vid >> 3, kg = (vid & 7) * 8;
                int gr = row0 + m;
                __half h[8];
                if (gr < M) {
                    const float* Ar = emb + rs[m] + k0 + kg;
                    float4 v0 = *(const float4*)(Ar);
                    float4 v1 = *(const float4*)(Ar + 4);
                    h[0] = __float2half_rn(v0.x); h[1] = __float2half_rn(v0.y);
                    h[2] = __float2half_rn(v0.z); h[3] = __float2half_rn(v0.w);
                    h[4] = __float2half_rn(v1.x); h[5] = __float2half_rn(v1.y);
                    h[6] = __float2half_rn(v1.z); h[7] = __float2half_rn(v1.w);
                } else {
                    #pragma unroll
                    for (int q = 0; q < 8; q++) h[q] = __float2half_rn(0.f);
                }
                *(int4*)&As[m][kg] = *(int4*)h;
            }
        } else {
            // fp16 A: 8192 halves = 1024 int4, 4/thread... (128*64/8=1024)
            #pragma unroll
            for (int t = 0; t < 4; t++) {
                int vid = tid + 256 * t;
                int m = vid >> 3, kg = (vid & 7) * 8;
                int gr = row0 + m;
                int4 v = make_int4(0, 0, 0, 0);
                if (gr < M) v = *(const int4*)(A16 + (size_t)gr * K + k0 + kg);
                *(int4*)&As[m][kg] = v;
            }
        }
        // ---- B tile 64 x 64 halves from Wt[n][k] ----
        #pragma unroll
        for (int t = 0; t < 2; t++) {
            int vid = tid + 256 * t;
            int nn = vid >> 3, kg = (vid & 7) * 8;
            int4 v = *(const int4*)(Wt + (size_t)(col0 + nn) * K + k0 + kg);
            *(int4*)&Bs[nn][kg] = v;
        }
        __syncthreads();

        int mt = wid * 16;
        #pragma unroll
        for (int ks = 0; ks < BKH; ks += 16) {
            unsigned a[4];
            a[0] = *(const unsigned*)&As[mt + g][ks + 2 * tig];
            a[1] = *(const unsigned*)&As[mt + g + 8][ks + 2 * tig];
            a[2] = *(const unsigned*)&As[mt + g][ks + 2 * tig + 8];
            a[3] = *(const unsigned*)&As[mt + g + 8][ks + 2 * tig + 8];
            #pragma unroll
            for (int j = 0; j < 8; j++) {
                unsigned b[2];
                b[0] = *(const unsigned*)&Bs[j * 8 + g][ks + 2 * tig];
                b[1] = *(const unsigned*)&Bs[j * 8 + g][ks + 2 * tig + 8];
                mma16(acc[j], a, b);
            }
        }
        __syncthreads();
    }

    // store C (fp16). acc[j]: c0,c1 at (g, j*8+2tig), c2,c3 at (g+8, ...)
    int r0 = row0 + wid * 16 + g;
    int r1 = r0 + 8;
    #pragma unroll
    for (int j = 0; j < 8; j++) {
        int c = col0 + j * 8 + tig * 2;
        if (r0 < M) *(__half2*)(Cout + (size_t)r0 * Ncols + c) = __floats2half2_rn(acc[j][0], acc[j][1]);
        if (r1 < M) *(__half2*)(Cout + (size_t)r1 * Ncols + c) = __floats2half2_rn(acc[j][2], acc[j][3]);
    }

    // fused alpha over this block's 64 cols (= one head)
    if (asrc_out) {
        int head = blockIdx.y;
        float s0 = 0.f, d0 = 0.f, s1 = 0.f, d1 = 0.f;
        #pragma unroll
        for (int j = 0; j < 8; j++) {
            int c = col0 + j * 8 + tig * 2;
            float w0 = att_src[c], w1 = att_src[c + 1];
            float v0 = att_dst[c], v1 = att_dst[c + 1];
            s0 += acc[j][0] * w0 + acc[j][1] * w1;
            d0 += acc[j][0] * v0 + acc[j][1] * v1;
            s1 += acc[j][2] * w0 + acc[j][3] * w1;
            d1 += acc[j][2] * v0 + acc[j][3] * v1;
        }
        #pragma unroll
        for (int o = 1; o <= 2; o <<= 1) {
            s0 += __shfl_xor_sync(0xFFFFFFFFu, s0, o);
            d0 += __shfl_xor_sync(0xFFFFFFFFu, d0, o);
            s1 += __shfl_xor_sync(0xFFFFFFFFu, s1, o);
            d1 += __shfl_xor_sync(0xFFFFFFFFu, d1, o);
        }
        if (tig == 0) {
            if (r0 < M) { asrc_out[r0 * heads + head] = s0; adst_out[r0 * heads + head] = d0; }
            if (r1 < M) { asrc_out[r1 * heads + head] = s1; adst_out[r1 * heads + head] = d1; }
        }
    }
}

// ---------------- layer1 aggregation: warp per dst node (fp16 gather) -------
__global__ __launch_bounds__(256) void k_agg1(
    const __half* __restrict__ h1, const float* __restrict__ b1, int n)
{
    int gw = (blockIdx.x * blockDim.x + threadIdx.x) >> 5;
    int lane = threadIdx.x & 31;
    if (gw >= n) return;
    int head = lane >> 3;
    int s0 = g_rowstart[gw], s1 = g_rowstart[gw + 1];
    float adst_n = g_adst1[gw * HEADS + head];
    float m = -1e30f;
    for (int e = s0; e < s1; e++) {
        int src = g_srcs[e];
        float l = g_asrc1[src * HEADS + head] + adst_n;
        l = l > 0.f ? l : SLOPE * l;
        m = fmaxf(m, l);
    }
    float acc[8] = {0, 0, 0, 0, 0, 0, 0, 0};
    float se = 0.f;
    for (int e = s0; e < s1; e++) {
        int src = g_srcs[e];
        float l = g_asrc1[src * HEADS + head] + adst_n;
        l = l > 0.f ? l : SLOPE * l;
        float p = __expf(l - m);
        se += p;
        int4 q = *(const int4*)(h1 + (size_t)src * C1 + lane * 8);
        float2 f0 = __half22float2(*(__half2*)&q.x);
        float2 f1 = __half22float2(*(__half2*)&q.y);
        float2 f2 = __half22float2(*(__half2*)&q.z);
        float2 f3 = __half22float2(*(__half2*)&q.w);
        acc[0] += p * f0.x; acc[1] += p * f0.y;
        acc[2] += p * f1.x; acc[3] += p * f1.y;
        acc[4] += p * f2.x; acc[5] += p * f2.y;
        acc[6] += p * f3.x; acc[7] += p * f3.y;
    }
    float inv = 1.f / se;
    __half h[8];
    #pragma unroll
    for (int j = 0; j < 8; j++) {
        int c = lane * 8 + j;
        float v = acc[j] * inv + b1[c];
        h[j] = __float2half_rn(v > 0.f ? v : expm1f(v));
    }
    *(int4*)(g_x2 + (size_t)gw * C1 + lane * 8) = *(int4*)h;
}

// ---------------- layer2 aggregation fused with gate MLP + global max -------
__global__ __launch_bounds__(256) void k_agg2gate(
    const __half* __restrict__ h2, const float* __restrict__ b2,
    const float* __restrict__ gW1, const float* __restrict__ gb1,
    const float* __restrict__ gW2, const float* __restrict__ gb2, int n)
{
    __shared__ float Ws[DHID * DHID];
    __shared__ float xr[8][DHID];
    __shared__ unsigned bmax;
    int tid = threadIdx.x;
    for (int i = tid; i < DHID * DHID; i += 256) Ws[i] = gW1[i];
    if (tid == 0) bmax = 0u;
    int w = tid >> 5, lane = tid & 31;
    int node = blockIdx.x * 8 + w;
    if (node < n) {
        int s0 = g_rowstart[node], s1 = g_rowstart[node + 1];
        float adst_n = g_adst2[node];
        float m = -1e30f;
        for (int e = s0; e < s1; e++) {
            int src = g_srcs[e];
            float l = g_asrc2[src] + adst_n;
            l = l > 0.f ? l : SLOPE * l;
            m = fmaxf(m, l);
        }
        float a0 = 0.f, a1 = 0.f, se = 0.f;
        for (int e = s0; e < s1; e++) {
            int src = g_srcs[e];
            float l = g_asrc2[src] + adst_n;
            l = l > 0.f ? l : SLOPE * l;
            float p = __expf(l - m);
            se += p;
            float2 f = __half22float2(*(const __half2*)(h2 + (size_t)src * DHID + lane * 2));
            a0 += p * f.x; a1 += p * f.y;
        }
        float inv = 1.f / se;
        float o0 = a0 * inv + b2[lane * 2];
        float o1 = a1 * inv + b2[lane * 2 + 1];
        o0 = o0 > 0.f ? o0 : expm1f(o0);
        o1 = o1 > 0.f ? o1 : expm1f(o1);
        g_x3[(size_t)node * DHID + lane * 2]     = o0;
        g_x3[(size_t)node * DHID + lane * 2 + 1] = o1;
        xr[w][lane * 2] = o0; xr[w][lane * 2 + 1] = o1;
    }
    __syncthreads();
    if (node < n) {
        float a0 = gb1[lane], a1 = gb1[lane + 32];
        #pragma unroll 8
        for (int k = 0; k < DHID; k++) {
            float xv = xr[w][k];
            a0 += xv * Ws[k * DHID + lane];
            a1 += xv * Ws[k * DHID + lane + 32];
        }
        a0 = fmaxf(a0, 0.f); a1 = fmaxf(a1, 0.f);
        float gv = a0 * gW2[lane] + a1 * gW2[lane + 32];
        #pragma unroll
        for (int o = 16; o; o >>= 1) gv += __shfl_xor_sync(0xFFFFFFFFu, gv, o);
        if (lane == 0) {
            gv += gb2[0];
            g_gate[node] = gv;
            atomicMax(&bmax, enc_f(gv));
        }
    }
    __syncthreads();
    if (tid == 0) atomicMax(&g_gmax_enc, bmax);
}

// ---------------- final pool + re-zero deg for next replay ------------------
__global__ void k_pool(float* __restrict__ out, int n) {
    int gt = blockIdx.x * 256 + threadIdx.x;
    for (int i = gt; i < n; i += DHID * 256) g_deg[i] = 0;

    __shared__ float red[256];
    __shared__ float redw[256];
    int c = blockIdx.x;
    int tid = threadIdx.x;
    float gmax = dec_f(g_gmax_enc);
    float s = 0.f, sw = 0.f;
    for (int i = tid; i < n; i += 256) {
        float w = __expf(g_gate[i] - gmax);
        s += w * g_x3[(size_t)i * DHID + c];
        sw += w;
    }
    red[tid] = s; redw[tid] = sw;
    __syncthreads();
    for (int o = 128; o; o >>= 1) {
        if (tid < o) { red[tid] += red[tid + o]; redw[tid] += redw[tid + o]; }
        __syncthreads();
    }
    if (tid == 0) out[c] = red[0] / redw[0];
}

// ---------------- launch ----------------
extern "C" void kernel_launch(void* const* d_in, const int* in_sizes, int n_in,
                              void* d_out, int out_size) {
    const int*   node_idxs = (const int*)  d_in[0];
    const int*   edge_idx  = (const int*)  d_in[1];
    const float* emb       = (const float*)d_in[2];
    const float* W1        = (const float*)d_in[3];
    const float* att_src1  = (const float*)d_in[4];
    const float* att_dst1  = (const float*)d_in[5];
    const float* b1        = (const float*)d_in[6];
    const float* W2        = (const float*)d_in[7];
    const float* att_src2  = (const float*)d_in[8];
    const float* att_dst2  = (const float*)d_in[9];
    const float* b2        = (const float*)d_in[10];
    const float* gW1       = (const float*)d_in[11];
    const float* gb1       = (const float*)d_in[12];
    const float* gW2       = (const float*)d_in[13];
    const float* gb2       = (const float*)d_in[14];
    float* out = (float*)d_out;

    int n = in_sizes[0];
    int E = in_sizes[1] / 2;
    int ET = E + n;

    __half *h1, *x2, *h2, *W1t, *W2t;
    float *as1, *ad1, *as2, *ad2;
    cudaGetSymbolAddress((void**)&h1, g_h1);
    cudaGetSymbolAddress((void**)&x2, g_x2);
    cudaGetSymbolAddress((void**)&h2, g_h2);
    cudaGetSymbolAddress((void**)&W1t, g_W1t);
    cudaGetSymbolAddress((void**)&W2t, g_W2t);
    cudaGetSymbolAddress((void**)&as1, g_asrc1);
    cudaGetSymbolAddress((void**)&ad1, g_adst1);
    cudaGetSymbolAddress((void**)&as2, g_asrc2);
    cudaGetSymbolAddress((void**)&ad2, g_adst2);

    int warpBlocks = (n * 32 + 255) / 256;

    // weight prep + CSR build
    k_prepw<<<64, 256>>>(W1, W2);
    k_count<<<(E / 4 + 256) / 256 + 1, 256>>>(edge_idx, E);
    k_scan<<<1, 1024>>>(n);
    k_fill<<<(ET / 4 + 256) / 256 + 1, 256>>>(edge_idx, E, n);

    // layer 1: gathered fp16 GEMM + fused alpha
    dim3 g1((n + BM - 1) / BM, C1 / BN);
    k_gemm_f16<<<g1, 256>>>(nullptr, W1t, h1, n, DIM, C1, node_idxs, emb,
                            att_src1, att_dst1, as1, ad1, HEADS);
    k_agg1<<<warpBlocks, 256>>>(h1, b1, n);

    // layer 2: fp16 GEMM + fused alpha
    dim3 g2((n + BM - 1) / BM, 1);
    k_gemm_f16<<<g2, 256>>>(x2, W2t, h2, n, C1, DHID, nullptr, nullptr,
                            att_src2, att_dst2, as2, ad2, 1);
    k_agg2gate<<<(n + 7) / 8, 256>>>(h2, b2, gW1, gb1, gW2, gb2, n);

    // pool
    k_pool<<<DHID, 256>>>(out, n);
}

// round 5
// speedup vs baseline: 1.9456x; 1.1515x over previous
#include <cuda_runtime.h>
#include <cuda_fp16.h>
#include <math.h>

#define DHID    64
#define HEADS   4
#define C1      256
#define DIM     128
#define SLOPE   0.2f

#define MAXN    20480
#define MAXET   345088

// ---------------- scratch ----------------
__device__ __half g_h1[MAXN * C1];
__device__ __half g_x2[MAXN * C1];
__device__ __half g_h2[MAXN * DHID];
__device__ float  g_x3[MAXN * DHID];
__device__ float  g_asrc1[MAXN * HEADS];
__device__ float  g_adst1[MAXN * HEADS];
__device__ float  g_asrc2[MAXN];
__device__ float  g_adst2[MAXN];
__device__ int    g_deg[MAXN];         // zeroed initially; re-zeroed by k_pool
__device__ int    g_cursor[MAXN];
__device__ int    g_rowstart[MAXN + 1];
__device__ int    g_srcs[MAXET];
__device__ float  g_gate[MAXN];
__device__ unsigned g_gmax_enc;
__device__ __half g_W1t[C1 * DIM];
__device__ __half g_W2t[DHID * C1];

__device__ __forceinline__ unsigned enc_f(float f) {
    unsigned b = __float_as_uint(f);
    return (b & 0x80000000u) ? ~b : (b | 0x80000000u);
}
__device__ __forceinline__ float dec_f(unsigned e) {
    unsigned b = (e & 0x80000000u) ? (e ^ 0x80000000u) : ~e;
    return __uint_as_float(b);
}

// ---------------- merged: edge-degree count + weight transpose/convert ------
__global__ void k_prep_count(const int* __restrict__ ei, int E,
                             const float* __restrict__ W1, const float* __restrict__ W2) {
    int t = blockIdx.x * blockDim.x + threadIdx.x;
    int total = gridDim.x * blockDim.x;
    int base = t * 4;
    if (base + 3 < E) {
        int4 d = *(const int4*)(ei + E + base);
        atomicAdd(&g_deg[d.x], 1);
        atomicAdd(&g_deg[d.y], 1);
        atomicAdd(&g_deg[d.z], 1);
        atomicAdd(&g_deg[d.w], 1);
    } else {
        for (int q = 0; q < 4; q++) {
            int i = base + q;
            if (i < E) atomicAdd(&g_deg[ei[E + i]], 1);
        }
    }
    // W1: [128][256] -> W1t [256][128]
    for (int i = t; i < DIM * C1; i += total) {
        int k = i / C1, nn = i % C1;
        g_W1t[nn * DIM + k] = __float2half_rn(W1[i]);
    }
    // W2: [256][64] -> W2t [64][256]
    for (int i = t; i < C1 * DHID; i += total) {
        int k = i / DHID, nn = i % DHID;
        g_W2t[nn * C1 + k] = __float2half_rn(W2[i]);
    }
}

// ---------------- parallel scan (1024 threads) ----------------
__global__ void k_scan(int n) {
    __shared__ int warpsum[32];
    int tid = threadIdx.x;
    if (tid == 0) g_gmax_enc = 0u;
    int chunk = (n + 1023) / 1024;
    int s0 = tid * chunk, s1 = min(s0 + chunk, n);
    int sum = 0;
    for (int i = s0; i < s1; i++) sum += g_deg[i] + 1;   // +1 self loop
    int lane = tid & 31, wid = tid >> 5;
    int v = sum;
    #pragma unroll
    for (int o = 1; o < 32; o <<= 1) {
        int u = __shfl_up_sync(0xFFFFFFFFu, v, o);
        if (lane >= o) v += u;
    }
    if (lane == 31) warpsum[wid] = v;
    __syncthreads();
    if (wid == 0) {
        int wv = warpsum[lane];
        #pragma unroll
        for (int o = 1; o < 32; o <<= 1) {
            int u = __shfl_up_sync(0xFFFFFFFFu, wv, o);
            if (lane >= o) wv += u;
        }
        warpsum[lane] = wv;
    }
    __syncthreads();
    int excl = v - sum + (wid > 0 ? warpsum[wid - 1] : 0);
    int run = excl;
    for (int i = s0; i < s1; i++) {
        g_rowstart[i] = run;
        g_cursor[i] = run;
        run += g_deg[i] + 1;
    }
    if (tid == 1023) g_rowstart[n] = run;
}

__global__ void k_fill(const int* __restrict__ ei, int E, int n) {
    int base = (blockIdx.x * blockDim.x + threadIdx.x) * 4;
    int ET = E + n;
    if (base + 3 < E) {
        int4 s = *(const int4*)(ei + base);
        int4 d = *(const int4*)(ei + E + base);
        g_srcs[atomicAdd(&g_cursor[d.x], 1)] = s.x;
        g_srcs[atomicAdd(&g_cursor[d.y], 1)] = s.y;
        g_srcs[atomicAdd(&g_cursor[d.z], 1)] = s.z;
        g_srcs[atomicAdd(&g_cursor[d.w], 1)] = s.w;
    } else {
        for (int t = 0; t < 4; t++) {
            int i = base + t;
            if (i >= ET) break;
            int src, dst;
            if (i < E) { src = ei[i]; dst = ei[E + i]; } else { src = dst = i - E; }
            g_srcs[atomicAdd(&g_cursor[dst], 1)] = src;
        }
    }
}

// ---------------- fp16 tensor-core GEMM + fused alpha epilogue --------------
#define BM 128
#define BN 64
#define BKH 64

__device__ __forceinline__ void mma16(float* d, const unsigned* a, const unsigned* b) {
    asm("mma.sync.aligned.m16n8k16.row.col.f32.f16.f16.f32 "
        "{%0,%1,%2,%3}, {%4,%5,%6,%7}, {%8,%9}, {%0,%1,%2,%3};"
        : "+f"(d[0]), "+f"(d[1]), "+f"(d[2]), "+f"(d[3])
        : "r"(a[0]), "r"(a[1]), "r"(a[2]), "r"(a[3]), "r"(b[0]), "r"(b[1]));
}

__global__ __launch_bounds__(256) void k_gemm_f16(
    const __half* __restrict__ A16, const __half* __restrict__ Wt,
    __half* __restrict__ Cout, int M, int K, int Ncols,
    const int* __restrict__ ridx, const float* __restrict__ emb,
    const float* __restrict__ att_src, const float* __restrict__ att_dst,
    float* __restrict__ asrc_out, float* __restrict__ adst_out, int heads)
{
    __shared__ __half As[BM][BKH + 8];
    __shared__ __half Bs[BN][BKH + 8];
    __shared__ int rs[BM];
    int tid = threadIdx.x;
    int row0 = blockIdx.x * BM;
    int col0 = blockIdx.y * BN;
    int wid = tid >> 5, lane = tid & 31;
    int g = lane >> 2, tig = lane & 3;

    if (ridx && tid < BM) {
        int r = row0 + tid;
        rs[tid] = (r < M) ? ridx[r] * K : 0;
    }
    float acc[8][4] = {};
    __syncthreads();

    for (int k0 = 0; k0 < K; k0 += BKH) {
        if (ridx) {
            #pragma unroll
            for (int t = 0; t < 4; t++) {
                int vid = tid + 256 * t;
                int m = vid >> 3, kg = (vid & 7) * 8;
                int gr = row0 + m;
                __half h[8];
                if (gr < M) {
                    const float* Ar = emb + rs[m] + k0 + kg;
                    float4 v0 = *(const float4*)(Ar);
                    float4 v1 = *(const float4*)(Ar + 4);
                    h[0] = __float2half_rn(v0.x); h[1] = __float2half_rn(v0.y);
                    h[2] = __float2half_rn(v0.z); h[3] = __float2half_rn(v0.w);
                    h[4] = __float2half_rn(v1.x); h[5] = __float2half_rn(v1.y);
                    h[6] = __float2half_rn(v1.z); h[7] = __float2half_rn(v1.w);
                } else {
                    #pragma unroll
                    for (int q = 0; q < 8; q++) h[q] = __float2half_rn(0.f);
                }
                *(int4*)&As[m][kg] = *(int4*)h;
            }
        } else {
            #pragma unroll
            for (int t = 0; t < 4; t++) {
                int vid = tid + 256 * t;
                int m = vid >> 3, kg = (vid & 7) * 8;
                int gr = row0 + m;
                int4 v = make_int4(0, 0, 0, 0);
                if (gr < M) v = *(const int4*)(A16 + (size_t)gr * K + k0 + kg);
                *(int4*)&As[m][kg] = v;
            }
        }
        #pragma unroll
        for (int t = 0; t < 2; t++) {
            int vid = tid + 256 * t;
            int nn = vid >> 3, kg = (vid & 7) * 8;
            int4 v = *(const int4*)(Wt + (size_t)(col0 + nn) * K + k0 + kg);
            *(int4*)&Bs[nn][kg] = v;
        }
        __syncthreads();

        int mt = wid * 16;
        #pragma unroll
        for (int ks = 0; ks < BKH; ks += 16) {
            unsigned a[4];
            a[0] = *(const unsigned*)&As[mt + g][ks + 2 * tig];
            a[1] = *(const unsigned*)&As[mt + g + 8][ks + 2 * tig];
            a[2] = *(const unsigned*)&As[mt + g][ks + 2 * tig + 8];
            a[3] = *(const unsigned*)&As[mt + g + 8][ks + 2 * tig + 8];
            #pragma unroll
            for (int j = 0; j < 8; j++) {
                unsigned b[2];
                b[0] = *(const unsigned*)&Bs[j * 8 + g][ks + 2 * tig];
                b[1] = *(const unsigned*)&Bs[j * 8 + g][ks + 2 * tig + 8];
                mma16(acc[j], a, b);
            }
        }
        __syncthreads();
    }

    int r0 = row0 + wid * 16 + g;
    int r1 = r0 + 8;
    #pragma unroll
    for (int j = 0; j < 8; j++) {
        int c = col0 + j * 8 + tig * 2;
        if (r0 < M) *(__half2*)(Cout + (size_t)r0 * Ncols + c) = __floats2half2_rn(acc[j][0], acc[j][1]);
        if (r1 < M) *(__half2*)(Cout + (size_t)r1 * Ncols + c) = __floats2half2_rn(acc[j][2], acc[j][3]);
    }

    if (asrc_out) {
        int head = blockIdx.y;
        float s0 = 0.f, d0 = 0.f, s1 = 0.f, d1 = 0.f;
        #pragma unroll
        for (int j = 0; j < 8; j++) {
            int c = col0 + j * 8 + tig * 2;
            float w0 = att_src[c], w1 = att_src[c + 1];
            float v0 = att_dst[c], v1 = att_dst[c + 1];
            s0 += acc[j][0] * w0 + acc[j][1] * w1;
            d0 += acc[j][0] * v0 + acc[j][1] * v1;
            s1 += acc[j][2] * w0 + acc[j][3] * w1;
            d1 += acc[j][2] * v0 + acc[j][3] * v1;
        }
        #pragma unroll
        for (int o = 1; o <= 2; o <<= 1) {
            s0 += __shfl_xor_sync(0xFFFFFFFFu, s0, o);
            d0 += __shfl_xor_sync(0xFFFFFFFFu, d0, o);
            s1 += __shfl_xor_sync(0xFFFFFFFFu, s1, o);
            d1 += __shfl_xor_sync(0xFFFFFFFFu, d1, o);
        }
        if (tig == 0) {
            if (r0 < M) { asrc_out[r0 * heads + head] = s0; adst_out[r0 * heads + head] = d0; }
            if (r1 < M) { asrc_out[r1 * heads + head] = s1; adst_out[r1 * heads + head] = d1; }
        }
    }
}

// ---------------- layer1 aggregation: single pass (no max), 2x unrolled -----
__global__ __launch_bounds__(256) void k_agg1(
    const __half* __restrict__ h1, const float* __restrict__ b1, int n)
{
    int gw = (blockIdx.x * blockDim.x + threadIdx.x) >> 5;
    int lane = threadIdx.x & 31;
    if (gw >= n) return;
    int head = lane >> 3;
    int s0 = g_rowstart[gw], s1 = g_rowstart[gw + 1];
    float adst_n = g_adst1[gw * HEADS + head];
    float acc[8] = {0, 0, 0, 0, 0, 0, 0, 0};
    float se = 0.f;
    int e = s0;
    for (; e + 2 <= s1; e += 2) {
        int sa = g_srcs[e], sb = g_srcs[e + 1];
        float la = g_asrc1[sa * HEADS + head] + adst_n;
        float lb = g_asrc1[sb * HEADS + head] + adst_n;
        int4 qa = *(const int4*)(h1 + (size_t)sa * C1 + lane * 8);
        int4 qb = *(const int4*)(h1 + (size_t)sb * C1 + lane * 8);
        la = la > 0.f ? la : SLOPE * la;
        lb = lb > 0.f ? lb : SLOPE * lb;
        float pa = __expf(la), pb = __expf(lb);
        se += pa + pb;
        float2 f;
        f = __half22float2(*(__half2*)&qa.x); acc[0] += pa * f.x; acc[1] += pa * f.y;
        f = __half22float2(*(__half2*)&qa.y); acc[2] += pa * f.x; acc[3] += pa * f.y;
        f = __half22float2(*(__half2*)&qa.z); acc[4] += pa * f.x; acc[5] += pa * f.y;
        f = __half22float2(*(__half2*)&qa.w); acc[6] += pa * f.x; acc[7] += pa * f.y;
        f = __half22float2(*(__half2*)&qb.x); acc[0] += pb * f.x; acc[1] += pb * f.y;
        f = __half22float2(*(__half2*)&qb.y); acc[2] += pb * f.x; acc[3] += pb * f.y;
        f = __half22float2(*(__half2*)&qb.z); acc[4] += pb * f.x; acc[5] += pb * f.y;
        f = __half22float2(*(__half2*)&qb.w); acc[6] += pb * f.x; acc[7] += pb * f.y;
    }
    if (e < s1) {
        int sa = g_srcs[e];
        float la = g_asrc1[sa * HEADS + head] + adst_n;
        la = la > 0.f ? la : SLOPE * la;
        float pa = __expf(la);
        se += pa;
        int4 qa = *(const int4*)(h1 + (size_t)sa * C1 + lane * 8);
        float2 f;
        f = __half22float2(*(__half2*)&qa.x); acc[0] += pa * f.x; acc[1] += pa * f.y;
        f = __half22float2(*(__half2*)&qa.y); acc[2] += pa * f.x; acc[3] += pa * f.y;
        f = __half22float2(*(__half2*)&qa.z); acc[4] += pa * f.x; acc[5] += pa * f.y;
        f = __half22float2(*(__half2*)&qa.w); acc[6] += pa * f.x; acc[7] += pa * f.y;
    }
    float inv = 1.f / se;
    __half h[8];
    #pragma unroll
    for (int j = 0; j < 8; j++) {
        int c = lane * 8 + j;
        float v = acc[j] * inv + b1[c];
        h[j] = __float2half_rn(v > 0.f ? v : expm1f(v));
    }
    *(int4*)(g_x2 + (size_t)gw * C1 + lane * 8) = *(int4*)h;
}

// ---------------- layer2 aggregation + gate MLP + global max ----------------
__global__ __launch_bounds__(256) void k_agg2gate(
    const __half* __restrict__ h2, const float* __restrict__ b2,
    const float* __restrict__ gW1, const float* __restrict__ gb1,
    const float* __restrict__ gW2, const float* __restrict__ gb2, int n)
{
    __shared__ float Ws[DHID * DHID];
    __shared__ float xr[8][DHID];
    __shared__ unsigned bmax;
    int tid = threadIdx.x;
    for (int i = tid; i < DHID * DHID; i += 256) Ws[i] = gW1[i];
    if (tid == 0) bmax = 0u;
    int w = tid >> 5, lane = tid & 31;
    int node = blockIdx.x * 8 + w;
    if (node < n) {
        int s0 = g_rowstart[node], s1 = g_rowstart[node + 1];
        float adst_n = g_adst2[node];
        float a0 = 0.f, a1 = 0.f, se = 0.f;
        int e = s0;
        for (; e + 2 <= s1; e += 2) {
            int sa = g_srcs[e], sb = g_srcs[e + 1];
            float la = g_asrc2[sa] + adst_n;
            float lb = g_asrc2[sb] + adst_n;
            __half2 ha = *(const __half2*)(h2 + (size_t)sa * DHID + lane * 2);
            __half2 hb = *(const __half2*)(h2 + (size_t)sb * DHID + lane * 2);
            la = la > 0.f ? la : SLOPE * la;
            lb = lb > 0.f ? lb : SLOPE * lb;
            float pa = __expf(la), pb = __expf(lb);
            se += pa + pb;
            float2 fa = __half22float2(ha), fb = __half22float2(hb);
            a0 += pa * fa.x + pb * fb.x;
            a1 += pa * fa.y + pb * fb.y;
        }
        if (e < s1) {
            int sa = g_srcs[e];
            float la = g_asrc2[sa] + adst_n;
            la = la > 0.f ? la : SLOPE * la;
            float pa = __expf(la);
            se += pa;
            float2 fa = __half22float2(*(const __half2*)(h2 + (size_t)sa * DHID + lane * 2));
            a0 += pa * fa.x; a1 += pa * fa.y;
        }
        float inv = 1.f / se;
        float o0 = a0 * inv + b2[lane * 2];
        float o1 = a1 * inv + b2[lane * 2 + 1];
        o0 = o0 > 0.f ? o0 : expm1f(o0);
        o1 = o1 > 0.f ? o1 : expm1f(o1);
        g_x3[(size_t)node * DHID + lane * 2]     = o0;
        g_x3[(size_t)node * DHID + lane * 2 + 1] = o1;
        xr[w][lane * 2] = o0; xr[w][lane * 2 + 1] = o1;
    }
    __syncthreads();
    if (node < n) {
        float a0 = gb1[lane], a1 = gb1[lane + 32];
        #pragma unroll 8
        for (int k = 0; k < DHID; k++) {
            float xv = xr[w][k];
            a0 += xv * Ws[k * DHID + lane];
            a1 += xv * Ws[k * DHID + lane + 32];
        }
        a0 = fmaxf(a0, 0.f); a1 = fmaxf(a1, 0.f);
        float gv = a0 * gW2[lane] + a1 * gW2[lane + 32];
        #pragma unroll
        for (int o = 16; o; o >>= 1) gv += __shfl_xor_sync(0xFFFFFFFFu, gv, o);
        if (lane == 0) {
            gv += gb2[0];
            g_gate[node] = gv;
            atomicMax(&bmax, enc_f(gv));
        }
    }
    __syncthreads();
    if (tid == 0) atomicMax(&g_gmax_enc, bmax);
}

// ---------------- final pool + re-zero deg for next replay ------------------
__global__ void k_pool(float* __restrict__ out, int n) {
    int gt = blockIdx.x * 256 + threadIdx.x;
    for (int i = gt; i < n; i += DHID * 256) g_deg[i] = 0;

    __shared__ float red[256];
    __shared__ float redw[256];
    int c = blockIdx.x;
    int tid = threadIdx.x;
    float gmax = dec_f(g_gmax_enc);
    float s = 0.f, sw = 0.f;
    for (int i = tid; i < n; i += 256) {
        float w = __expf(g_gate[i] - gmax);
        s += w * g_x3[(size_t)i * DHID + c];
        sw += w;
    }
    red[tid] = s; redw[tid] = sw;
    __syncthreads();
    for (int o = 128; o; o >>= 1) {
        if (tid < o) { red[tid] += red[tid + o]; redw[tid] += redw[tid + o]; }
        __syncthreads();
    }
    if (tid == 0) out[c] = red[0] / redw[0];
}

// ---------------- launch ----------------
extern "C" void kernel_launch(void* const* d_in, const int* in_sizes, int n_in,
                              void* d_out, int out_size) {
    const int*   node_idxs = (const int*)  d_in[0];
    const int*   edge_idx  = (const int*)  d_in[1];
    const float* emb       = (const float*)d_in[2];
    const float* W1        = (const float*)d_in[3];
    const float* att_src1  = (const float*)d_in[4];
    const float* att_dst1  = (const float*)d_in[5];
    const float* b1        = (const float*)d_in[6];
    const float* W2        = (const float*)d_in[7];
    const float* att_src2  = (const float*)d_in[8];
    const float* att_dst2  = (const float*)d_in[9];
    const float* b2        = (const float*)d_in[10];
    const float* gW1       = (const float*)d_in[11];
    const float* gb1       = (const float*)d_in[12];
    const float* gW2       = (const float*)d_in[13];
    const float* gb2       = (const float*)d_in[14];
    float* out = (float*)d_out;

    int n = in_sizes[0];
    int E = in_sizes[1] / 2;
    int ET = E + n;

    __half *h1, *x2, *h2, *W1t, *W2t;
    float *as1, *ad1, *as2, *ad2;
    cudaGetSymbolAddress((void**)&h1, g_h1);
    cudaGetSymbolAddress((void**)&x2, g_x2);
    cudaGetSymbolAddress((void**)&h2, g_h2);
    cudaGetSymbolAddress((void**)&W1t, g_W1t);
    cudaGetSymbolAddress((void**)&W2t, g_W2t);
    cudaGetSymbolAddress((void**)&as1, g_asrc1);
    cudaGetSymbolAddress((void**)&ad1, g_adst1);
    cudaGetSymbolAddress((void**)&as2, g_asrc2);
    cudaGetSymbolAddress((void**)&ad2, g_adst2);

    int warpBlocks = (n * 32 + 255) / 256;

    // CSR build + weight prep (merged)
    k_prep_count<<<(E / 4 + 256) / 256 + 1, 256>>>(edge_idx, E, W1, W2);
    k_scan<<<1, 1024>>>(n);
    k_fill<<<(ET / 4 + 256) / 256 + 1, 256>>>(edge_idx, E, n);

    // layer 1
    dim3 g1((n + BM - 1) / BM, C1 / BN);
    k_gemm_f16<<<g1, 256>>>(nullptr, W1t, h1, n, DIM, C1, node_idxs, emb,
                            att_src1, att_dst1, as1, ad1, HEADS);
    k_agg1<<<warpBlocks, 256>>>(h1, b1, n);

    // layer 2
    dim3 g2((n + BM - 1) / BM, 1);
    k_gemm_f16<<<g2, 256>>>(x2, W2t, h2, n, C1, DHID, nullptr, nullptr,
                            att_src2, att_dst2, as2, ad2, 1);
    k_agg2gate<<<(n + 7) / 8, 256>>>(h2, b2, gW1, gb1, gW2, gb2, n);

    // pool
    k_pool<<<DHID, 256>>>(out, n);
}